// round 2
// baseline (speedup 1.0000x reference)
#include <cuda_runtime.h>

#define BB    4
#define NQ    2048
#define DIM   1024
#define HEADS 16
#define DH    64
#define INNER 1024
#define NCOLS 3072

#define A_ELEMS (BB*NQ*INNER)        // 8388608
#define M_ELEMS (BB*HEADS*DH*DH)     // 262144
#define Z_ELEMS (BB*HEADS*DH)        // 4096

// scratch: q,k,v in [b,h,n,d] layout
__device__ float g_q[BB*HEADS*NQ*DH];
__device__ float g_k[BB*HEADS*NQ*DH];
__device__ float g_v[BB*HEADS*NQ*DH];

// ---------------------------------------------------------------------------
// Kernel 1: qkv = x @ W_qkv, scattered into g_q/g_k/g_v [b,h,n,d]
// C[8192,3072] = x[8192,1024] @ W[1024,3072]
// 64x64 tile, BK=16, 256 threads, 4x4 per thread.
// ---------------------------------------------------------------------------
__global__ __launch_bounds__(256)
void qkv_gemm_kernel(const float* __restrict__ x, const float* __restrict__ W) {
    __shared__ float As[16][64];   // As[k][m]
    __shared__ float Bs[16][64];   // Bs[k][n]
    const int tid = threadIdx.x;
    const int bm = blockIdx.y * 64;
    const int bn = blockIdx.x * 64;
    const int tx = tid & 15, ty = tid >> 4;

    const int a_m = tid >> 2;            // 0..63
    const int a_k = (tid & 3) << 2;      // 0,4,8,12
    const int b_k = tid >> 4;            // 0..15
    const int b_n = (tid & 15) << 2;     // 0..60

    float c[4][4] = {};
    const float* xp = x + (size_t)(bm + a_m) * DIM + a_k;
    const float* wp = W + (size_t)b_k * NCOLS + bn + b_n;

    for (int k0 = 0; k0 < DIM; k0 += 16) {
        float4 av = *(const float4*)(xp + k0);
        float4 bv = *(const float4*)(wp + (size_t)k0 * NCOLS);
        __syncthreads();
        As[a_k+0][a_m] = av.x;
        As[a_k+1][a_m] = av.y;
        As[a_k+2][a_m] = av.z;
        As[a_k+3][a_m] = av.w;
        *(float4*)&Bs[b_k][b_n] = bv;
        __syncthreads();
        #pragma unroll
        for (int kk = 0; kk < 16; kk++) {
            float4 a4 = *(const float4*)&As[kk][ty << 2];
            float4 b4 = *(const float4*)&Bs[kk][tx << 2];
            c[0][0] += a4.x*b4.x; c[0][1] += a4.x*b4.y; c[0][2] += a4.x*b4.z; c[0][3] += a4.x*b4.w;
            c[1][0] += a4.y*b4.x; c[1][1] += a4.y*b4.y; c[1][2] += a4.y*b4.z; c[1][3] += a4.y*b4.w;
            c[2][0] += a4.z*b4.x; c[2][1] += a4.z*b4.y; c[2][2] += a4.z*b4.z; c[2][3] += a4.z*b4.w;
            c[3][0] += a4.w*b4.x; c[3][1] += a4.w*b4.y; c[3][2] += a4.w*b4.z; c[3][3] += a4.w*b4.w;
        }
    }

    // epilogue scatter: bn multiple of 64, so part/head constant per CTA
    const int part = bn >> 10;                 // 0=q,1=k,2=v
    const int h    = (bn & 1023) >> 6;
    float* dst = (part == 0) ? g_q : (part == 1) ? g_k : g_v;
    #pragma unroll
    for (int i = 0; i < 4; i++) {
        int r  = bm + (ty << 2) + i;
        int b  = r >> 11;
        int n  = r & 2047;
        float4 v4 = make_float4(c[i][0], c[i][1], c[i][2], c[i][3]);
        size_t off = (((size_t)(b*HEADS + h) * NQ + n) * DH) + (tx << 2);
        *(float4*)&dst[off] = v4;
    }
}

// ---------------------------------------------------------------------------
// Kernel 2: flash attention + compressive-memory branch + gate -> A
// grid (16 qtiles, 16 heads, 4 batch), 128 threads, 1 thread = 1 query row.
// ---------------------------------------------------------------------------
__global__ __launch_bounds__(128, 2)
void attn_kernel(const float* __restrict__ M_in, const float* __restrict__ Z_in,
                 const float* __restrict__ beta_gate, float* __restrict__ outA) {
    __shared__ float Mt[DH][DH];   // Mt[v][d] = M[d][v]
    __shared__ float Zs[DH];
    __shared__ float Ks[32][DH];
    __shared__ float Vs[32][DH];

    const int tid = threadIdx.x;
    const int b = blockIdx.z, h = blockIdx.y;
    const int row = blockIdx.x * 128 + tid;
    const int bh = b * HEADS + h;

    const float* Mg = M_in + (size_t)bh * DH * DH;
    for (int e = tid; e < DH*DH; e += 128) {
        int d = e >> 6, v = e & 63;
        Mt[v][d] = Mg[e];
    }
    if (tid < DH) Zs[tid] = Z_in[bh*DH + tid];

    float q[DH];
    {
        const float4* qp = (const float4*)(g_q + ((size_t)bh*NQ + row)*DH);
        #pragma unroll
        for (int i = 0; i < 16; i++) {
            float4 t = qp[i];
            q[4*i] = t.x; q[4*i+1] = t.y; q[4*i+2] = t.z; q[4*i+3] = t.w;
        }
    }

    float o[DH];
    #pragma unroll
    for (int d = 0; d < DH; d++) o[d] = 0.f;
    float mrow = -1e30f, l = 0.f;

    const float* kg = g_k + (size_t)bh*NQ*DH;
    const float* vg = g_v + (size_t)bh*NQ*DH;

    for (int jt = 0; jt < NQ; jt += 32) {
        __syncthreads();
        #pragma unroll
        for (int i = 0; i < 4; i++) {
            int fidx = tid + 128*i;          // 0..511
            int j = fidx >> 4, dd = (fidx & 15) << 2;
            *(float4*)&Ks[j][dd] = *(const float4*)&kg[(size_t)(jt+j)*DH + dd];
            *(float4*)&Vs[j][dd] = *(const float4*)&vg[(size_t)(jt+j)*DH + dd];
        }
        __syncthreads();

        float s[32];
        float tmax = -1e30f;
        #pragma unroll
        for (int j = 0; j < 32; j++) {
            float acc = 0.f;
            const float4* k4 = (const float4*)Ks[j];
            #pragma unroll
            for (int dd = 0; dd < 16; dd++) {
                float4 kk4 = k4[dd];
                acc += q[4*dd]*kk4.x + q[4*dd+1]*kk4.y + q[4*dd+2]*kk4.z + q[4*dd+3]*kk4.w;
            }
            s[j] = acc * 0.125f;
            tmax = fmaxf(tmax, s[j]);
        }
        float mnew = fmaxf(mrow, tmax);
        float corr = __expf(mrow - mnew);
        l *= corr;
        #pragma unroll
        for (int d = 0; d < DH; d++) o[d] *= corr;
        #pragma unroll
        for (int j = 0; j < 32; j++) {
            float p = __expf(s[j] - mnew);
            l += p;
            const float4* v4 = (const float4*)Vs[j];
            #pragma unroll
            for (int dd = 0; dd < 16; dd++) {
                float4 vv = v4[dd];
                o[4*dd]   += p*vv.x;
                o[4*dd+1] += p*vv.y;
                o[4*dd+2] += p*vv.z;
                o[4*dd+3] += p*vv.w;
            }
        }
        mrow = mnew;
    }

    // memory branch: sigma(q) = q>0 ? q+1 : exp(q)
    float sq[DH];
    #pragma unroll
    for (int d = 0; d < DH; d++) sq[d] = (q[d] > 0.f) ? (q[d] + 1.f) : __expf(q[d]);
    float den = 0.f;
    #pragma unroll
    for (int d = 0; d < DH; d++) den += sq[d]*Zs[d];

    float gv = 1.f / (1.f + __expf(-beta_gate[h]));
    float inv_l = 1.f / l;
    float inv_den = 1.f / den;

    float* op = outA + ((size_t)(b*NQ + row)) * INNER + h*DH;
    #pragma unroll
    for (int v0 = 0; v0 < DH; v0 += 4) {
        float n0 = 0.f, n1 = 0.f, n2 = 0.f, n3 = 0.f;
        const float4* m0 = (const float4*)Mt[v0+0];
        const float4* m1 = (const float4*)Mt[v0+1];
        const float4* m2 = (const float4*)Mt[v0+2];
        const float4* m3 = (const float4*)Mt[v0+3];
        #pragma unroll
        for (int dd = 0; dd < 16; dd++) {
            float4 a = m0[dd], bq = m1[dd], cq = m2[dd], dq = m3[dd];
            n0 += sq[4*dd]*a.x  + sq[4*dd+1]*a.y  + sq[4*dd+2]*a.z  + sq[4*dd+3]*a.w;
            n1 += sq[4*dd]*bq.x + sq[4*dd+1]*bq.y + sq[4*dd+2]*bq.z + sq[4*dd+3]*bq.w;
            n2 += sq[4*dd]*cq.x + sq[4*dd+1]*cq.y + sq[4*dd+2]*cq.z + sq[4*dd+3]*cq.w;
            n3 += sq[4*dd]*dq.x + sq[4*dd+1]*dq.y + sq[4*dd+2]*dq.z + sq[4*dd+3]*dq.w;
        }
        float4 r;
        r.x = gv*(n0*inv_den) + (1.f-gv)*(o[v0+0]*inv_l);
        r.y = gv*(n1*inv_den) + (1.f-gv)*(o[v0+1]*inv_l);
        r.z = gv*(n2*inv_den) + (1.f-gv)*(o[v0+2]*inv_l);
        r.w = gv*(n3*inv_den) + (1.f-gv)*(o[v0+3]*inv_l);
        *(float4*)&op[v0] = r;
    }
}

// ---------------------------------------------------------------------------
// Kernel 3: state update. One CTA per (b,h), 256 threads, chunks of 32 rows.
// M_new = beta*M + sk^T @ (v - moment),  Z_new = beta*Z + sum_n sk
// ---------------------------------------------------------------------------
#define CN 32
__global__ __launch_bounds__(256)
void state_kernel(const float* __restrict__ M_in, const float* __restrict__ Z_in,
                  const float* __restrict__ beta_lin, float* __restrict__ out) {
    __shared__ float Ms[DH][DH];       // Ms[d][v]
    __shared__ float Zs[DH];
    __shared__ float sks[CN][DH];
    __shared__ float dvs[CN][DH];
    __shared__ float invden[CN];

    const int tid = threadIdx.x;
    const int bh = blockIdx.x;

    const float* Mg = M_in + (size_t)bh * DH * DH;
    for (int e = tid; e < DH*DH; e += 256) Ms[e >> 6][e & 63] = Mg[e];
    if (tid < DH) Zs[tid] = Z_in[bh*DH + tid];

    const float* kg = g_k + (size_t)bh*NQ*DH;
    const float* vg = g_v + (size_t)bh*NQ*DH;

    const int dgrp = tid >> 2;          // 0..63 : d row owned
    const int vb   = (tid & 3) << 4;    // v block start
    float macc[16];
    #pragma unroll
    for (int i = 0; i < 16; i++) macc[i] = 0.f;
    float zacc = 0.f;

    for (int n0 = 0; n0 < NQ; n0 += CN) {
        __syncthreads();
        #pragma unroll
        for (int i = 0; i < 2; i++) {
            int fidx = tid + 256*i;       // 0..511
            int n = fidx >> 4, dd = (fidx & 15) << 2;
            float4 kv = *(const float4*)&kg[(size_t)(n0+n)*DH + dd];
            kv.x = (kv.x > 0.f) ? (kv.x + 1.f) : __expf(kv.x);
            kv.y = (kv.y > 0.f) ? (kv.y + 1.f) : __expf(kv.y);
            kv.z = (kv.z > 0.f) ? (kv.z + 1.f) : __expf(kv.z);
            kv.w = (kv.w > 0.f) ? (kv.w + 1.f) : __expf(kv.w);
            *(float4*)&sks[n][dd] = kv;
            *(float4*)&dvs[n][dd] = *(const float4*)&vg[(size_t)(n0+n)*DH + dd];
        }
        __syncthreads();
        if (tid < CN) {
            float acc = 0.f;
            #pragma unroll
            for (int d = 0; d < DH; d++) acc += sks[tid][d]*Zs[d];
            invden[tid] = 1.f / acc;
        }
        __syncthreads();
        // moment & diff: CN*DH = 2048 entries / 256 threads = 8 each
        #pragma unroll
        for (int e = 0; e < 8; e++) {
            int idx = tid + 256*e;
            int n = idx >> 6, v = idx & 63;
            float acc = 0.f;
            #pragma unroll
            for (int d = 0; d < DH; d++) acc += sks[n][d]*Ms[d][v];
            dvs[n][v] -= acc * invden[n];
        }
        __syncthreads();
        // accumulate outer product
        #pragma unroll 4
        for (int n = 0; n < CN; n++) {
            float skdn = sks[n][dgrp];
            const float* dv = &dvs[n][vb];
            #pragma unroll
            for (int vv = 0; vv < 16; vv++) macc[vv] += skdn * dv[vv];
        }
        if (tid < DH) {
            #pragma unroll
            for (int n = 0; n < CN; n++) zacc += sks[n][tid];
        }
    }
    __syncthreads();

    float beta = 1.f / (1.f + __expf(-beta_lin[0]));
    beta = fminf(fmaxf(beta, 0.9f), 0.999f);

    float* mout = out + A_ELEMS + (size_t)bh * DH * DH;
    #pragma unroll
    for (int vv = 0; vv < 16; vv++)
        mout[dgrp*DH + vb + vv] = beta*Ms[dgrp][vb+vv] + macc[vv];
    if (tid < DH)
        out[A_ELEMS + M_ELEMS + bh*DH + tid] = beta*Zs[tid] + zacc;
}

// ---------------------------------------------------------------------------
extern "C" void kernel_launch(void* const* d_in, const int* in_sizes, int n_in,
                              void* d_out, int out_size) {
    const float* x         = (const float*)d_in[0];
    const float* M         = (const float*)d_in[1];
    const float* Z         = (const float*)d_in[2];
    const float* W         = (const float*)d_in[3];
    const float* beta_lin  = (const float*)d_in[4];
    const float* beta_gate = (const float*)d_in[5];
    float* out = (float*)d_out;

    qkv_gemm_kernel<<<dim3(NCOLS/64, (BB*NQ)/64), 256>>>(x, W);
    attn_kernel<<<dim3(NQ/128, HEADS, BB), 128>>>(M, Z, beta_gate, out);
    state_kernel<<<BB*HEADS, 256>>>(M, Z, beta_lin, out);
}

// round 3
// speedup vs baseline: 2.3244x; 2.3244x over previous
#include <cuda_runtime.h>

#define BB    4
#define NQ    2048
#define DIMK  1024
#define HEADS 16
#define DH    64
#define INNER 1024
#define NCOLS 3072

#define A_ELEMS (BB*NQ*INNER)
#define M_ELEMS (BB*HEADS*DH*DH)

__device__ float g_q[BB*HEADS*NQ*DH];
__device__ float g_k[BB*HEADS*NQ*DH];
__device__ float g_v[BB*HEADS*NQ*DH];

__device__ __forceinline__ unsigned f2tf(float f) {
    unsigned u; asm("cvt.rna.tf32.f32 %0, %1;" : "=r"(u) : "f"(f)); return u;
}
__device__ __forceinline__ void mma8(float* c, const unsigned* a, const unsigned* b) {
    asm volatile(
        "mma.sync.aligned.m16n8k8.row.col.f32.tf32.tf32.f32 "
        "{%0,%1,%2,%3}, {%4,%5,%6,%7}, {%8,%9}, {%0,%1,%2,%3};\n"
        : "+f"(c[0]), "+f"(c[1]), "+f"(c[2]), "+f"(c[3])
        : "r"(a[0]), "r"(a[1]), "r"(a[2]), "r"(a[3]), "r"(b[0]), "r"(b[1]));
}
__device__ __forceinline__ float sigma_f(float f) {
    return (f > 0.f) ? (f + 1.f) : __expf(f);
}

// ---------------------------------------------------------------------------
// Kernel 1: QKV GEMM (tf32 mma): C[8192,3072] = x @ W, scatter to g_q/g_k/g_v
// ---------------------------------------------------------------------------
__global__ __launch_bounds__(256)
void qkv_gemm(const float* __restrict__ x, const float* __restrict__ W) {
    __shared__ __align__(16) unsigned As[128*20];
    __shared__ __align__(16) unsigned Bs[16*136];

    const int tid  = threadIdx.x;
    const int bm   = blockIdx.y * 128, bn = blockIdx.x * 128;
    const int wid  = tid >> 5, lane = tid & 31;
    const int wm   = (wid & 1) * 64, wn = (wid >> 1) * 32;
    const int lr   = lane >> 2, lc = lane & 3;

    const int ar0 = tid >> 2;
    const int ac  = (tid & 3) << 2;
    const int bk0 = tid >> 5;
    const int bc  = (tid & 31) << 2;

    const float* ap0 = x + (size_t)(bm + ar0) * DIMK + ac;
    const float* ap1 = ap0 + (size_t)64 * DIMK;
    const float* bp0 = W + (size_t)bk0 * NCOLS + bn + bc;
    const float* bp1 = bp0 + (size_t)8 * NCOLS;

    float4 ra0 = *(const float4*)ap0;
    float4 ra1 = *(const float4*)ap1;
    float4 rb0 = *(const float4*)bp0;
    float4 rb1 = *(const float4*)bp1;

    float cacc[4][4][4];
    #pragma unroll
    for (int i = 0; i < 4; i++)
        #pragma unroll
        for (int j = 0; j < 4; j++) { cacc[i][j][0]=0.f; cacc[i][j][1]=0.f; cacc[i][j][2]=0.f; cacc[i][j][3]=0.f; }

    for (int kt = 0; kt < DIMK/16; ++kt) {
        unsigned* ad0 = &As[ar0*20 + ac];
        ad0[0]=f2tf(ra0.x); ad0[1]=f2tf(ra0.y); ad0[2]=f2tf(ra0.z); ad0[3]=f2tf(ra0.w);
        unsigned* ad1 = &As[(ar0+64)*20 + ac];
        ad1[0]=f2tf(ra1.x); ad1[1]=f2tf(ra1.y); ad1[2]=f2tf(ra1.z); ad1[3]=f2tf(ra1.w);
        *(uint4*)&Bs[bk0*136 + bc]     = make_uint4(f2tf(rb0.x), f2tf(rb0.y), f2tf(rb0.z), f2tf(rb0.w));
        *(uint4*)&Bs[(bk0+8)*136 + bc] = make_uint4(f2tf(rb1.x), f2tf(rb1.y), f2tf(rb1.z), f2tf(rb1.w));
        __syncthreads();

        if (kt + 1 < DIMK/16) {
            int ko = (kt + 1) * 16;
            ra0 = *(const float4*)(ap0 + ko);
            ra1 = *(const float4*)(ap1 + ko);
            rb0 = *(const float4*)(bp0 + (size_t)ko * NCOLS);
            rb1 = *(const float4*)(bp1 + (size_t)ko * NCOLS);
        }

        #pragma unroll
        for (int ks = 0; ks < 2; ++ks) {
            unsigned af[4][4];
            #pragma unroll
            for (int mt = 0; mt < 4; ++mt) {
                int r = wm + mt*16 + lr, k = ks*8 + lc;
                af[mt][0] = As[r*20 + k];
                af[mt][1] = As[(r+8)*20 + k];
                af[mt][2] = As[r*20 + k + 4];
                af[mt][3] = As[(r+8)*20 + k + 4];
            }
            unsigned bf[4][2];
            #pragma unroll
            for (int nt = 0; nt < 4; ++nt) {
                int c = wn + nt*8 + lr, k = ks*8 + lc;
                bf[nt][0] = Bs[k*136 + c];
                bf[nt][1] = Bs[(k+4)*136 + c];
            }
            #pragma unroll
            for (int mt = 0; mt < 4; ++mt)
                #pragma unroll
                for (int nt = 0; nt < 4; ++nt)
                    mma8(cacc[mt][nt], af[mt], bf[nt]);
        }
        __syncthreads();
    }

    #pragma unroll
    for (int mt = 0; mt < 4; ++mt) {
        int r0 = bm + wm + mt*16 + lr;
        #pragma unroll
        for (int nt = 0; nt < 4; ++nt) {
            int cg = bn + wn + nt*8 + 2*lc;
            int part = cg >> 10;
            float* dst = (part == 0) ? g_q : (part == 1) ? g_k : g_v;
            int hh = (cg >> 6) & (HEADS - 1);
            int dd = cg & 63;
            int bi = r0 >> 11, nn = r0 & 2047;
            size_t off = (((size_t)(bi*HEADS + hh) * NQ + nn) * DH) + dd;
            *(float2*)&dst[off] = make_float2(cacc[mt][nt][0], cacc[mt][nt][1]);
            int r1 = r0 + 8;
            bi = r1 >> 11; nn = r1 & 2047;
            off = (((size_t)(bi*HEADS + hh) * NQ + nn) * DH) + dd;
            *(float2*)&dst[off] = make_float2(cacc[mt][nt][2], cacc[mt][nt][3]);
        }
    }
}

// ---------------------------------------------------------------------------
// Kernel 2: tf32-mma flash attention + memory branch + gate
// 128 q rows/CTA, 8 warps, Bc=64. Dynamic smem.
// layout: Ks[64*68] | Vs[64*72] | Ps[128*68] | Zs[64]
// ---------------------------------------------------------------------------
#define ATT_SMEM_WORDS (64*68 + 64*72 + 128*68 + 64)
#define ATT_SMEM_BYTES (ATT_SMEM_WORDS*4)

__global__ __launch_bounds__(256)
void attn_k(const float* __restrict__ M_in, const float* __restrict__ Z_in,
            const float* __restrict__ beta_gate, float* __restrict__ outA) {
    extern __shared__ unsigned sm[];
    unsigned* Ks = sm;                 // [64][68]; reused for M^T in epilogue
    unsigned* Vs = Ks + 64*68;         // [64][72] row-major V
    unsigned* Ps = Vs + 64*72;         // [128][68]; stages Q first
    float*    Zs = (float*)(Ps + 128*68);

    const int tid = threadIdx.x, wid = tid >> 5, lane = tid & 31;
    const int lr = lane >> 2, lc = lane & 3;
    const int b = blockIdx.z, h = blockIdx.y, bh = b*HEADS + h;
    const int qb = blockIdx.x * 128;
    const int rowA = wid*16 + lr;

    const float* qg = g_q + ((size_t)bh*NQ + qb)*DH;
    const float* kg = g_k + (size_t)bh*NQ*DH;
    const float* vg = g_v + (size_t)bh*NQ*DH;

    // stage Q into Ps (coalesced), then extract A-fragments to registers
    for (int i = tid; i < 128*16; i += 256) {
        int r = i >> 4, c4 = (i & 15) << 2;
        float4 v = *(const float4*)(qg + (size_t)r*DH + c4);
        *(uint4*)&Ps[r*68 + c4] = make_uint4(f2tf(v.x), f2tf(v.y), f2tf(v.z), f2tf(v.w));
    }
    __syncthreads();
    unsigned qa[8][4];
    #pragma unroll
    for (int ks = 0; ks < 8; ++ks) {
        qa[ks][0] = Ps[rowA*68 + ks*8 + lc];
        qa[ks][1] = Ps[(rowA+8)*68 + ks*8 + lc];
        qa[ks][2] = Ps[rowA*68 + ks*8 + lc + 4];
        qa[ks][3] = Ps[(rowA+8)*68 + ks*8 + lc + 4];
    }

    float oacc[8][4];
    #pragma unroll
    for (int i = 0; i < 8; i++) { oacc[i][0]=0.f; oacc[i][1]=0.f; oacc[i][2]=0.f; oacc[i][3]=0.f; }
    float m1 = -1e30f, m2 = -1e30f, l1 = 0.f, l2 = 0.f;

    for (int jt = 0; jt < NQ; jt += 64) {
        __syncthreads();
        for (int i = tid; i < 64*16; i += 256) {
            int r = i >> 4, c4 = (i & 15) << 2;
            float4 kv = *(const float4*)(kg + (size_t)(jt + r)*DH + c4);
            *(uint4*)&Ks[r*68 + c4] = make_uint4(f2tf(kv.x), f2tf(kv.y), f2tf(kv.z), f2tf(kv.w));
            float4 vv = *(const float4*)(vg + (size_t)(jt + r)*DH + c4);
            *(uint4*)&Vs[r*72 + c4] = make_uint4(f2tf(vv.x), f2tf(vv.y), f2tf(vv.z), f2tf(vv.w));
        }
        __syncthreads();

        float sacc[8][4];
        #pragma unroll
        for (int i = 0; i < 8; i++) { sacc[i][0]=0.f; sacc[i][1]=0.f; sacc[i][2]=0.f; sacc[i][3]=0.f; }

        #pragma unroll
        for (int ks = 0; ks < 8; ++ks) {
            #pragma unroll
            for (int nt = 0; nt < 8; ++nt) {
                unsigned bf[2];
                const unsigned* kp = &Ks[(nt*8 + lr)*68 + ks*8 + lc];
                bf[0] = kp[0]; bf[1] = kp[4];
                mma8(sacc[nt], qa[ks], bf);
            }
        }

        const float sc = 0.125f;
        float tmax1 = -1e30f, tmax2 = -1e30f;
        #pragma unroll
        for (int nt = 0; nt < 8; ++nt) {
            tmax1 = fmaxf(tmax1, fmaxf(sacc[nt][0], sacc[nt][1]));
            tmax2 = fmaxf(tmax2, fmaxf(sacc[nt][2], sacc[nt][3]));
        }
        tmax1 = fmaxf(tmax1, __shfl_xor_sync(0xffffffffu, tmax1, 1));
        tmax1 = fmaxf(tmax1, __shfl_xor_sync(0xffffffffu, tmax1, 2));
        tmax2 = fmaxf(tmax2, __shfl_xor_sync(0xffffffffu, tmax2, 1));
        tmax2 = fmaxf(tmax2, __shfl_xor_sync(0xffffffffu, tmax2, 2));

        float mn1 = fmaxf(m1, tmax1*sc), mn2 = fmaxf(m2, tmax2*sc);
        float corr1 = __expf(m1 - mn1), corr2 = __expf(m2 - mn2);
        float rs1 = 0.f, rs2 = 0.f;
        #pragma unroll
        for (int nt = 0; nt < 8; ++nt) {
            float p0 = __expf(sacc[nt][0]*sc - mn1);
            float p1 = __expf(sacc[nt][1]*sc - mn1);
            float p2 = __expf(sacc[nt][2]*sc - mn2);
            float p3 = __expf(sacc[nt][3]*sc - mn2);
            rs1 += p0 + p1; rs2 += p2 + p3;
            *(uint2*)&Ps[rowA*68 + nt*8 + 2*lc]     = make_uint2(f2tf(p0), f2tf(p1));
            *(uint2*)&Ps[(rowA+8)*68 + nt*8 + 2*lc] = make_uint2(f2tf(p2), f2tf(p3));
        }
        rs1 += __shfl_xor_sync(0xffffffffu, rs1, 1);
        rs1 += __shfl_xor_sync(0xffffffffu, rs1, 2);
        rs2 += __shfl_xor_sync(0xffffffffu, rs2, 1);
        rs2 += __shfl_xor_sync(0xffffffffu, rs2, 2);
        l1 = l1*corr1 + rs1;
        l2 = l2*corr2 + rs2;
        #pragma unroll
        for (int nt = 0; nt < 8; ++nt) {
            oacc[nt][0] *= corr1; oacc[nt][1] *= corr1;
            oacc[nt][2] *= corr2; oacc[nt][3] *= corr2;
        }
        m1 = mn1; m2 = mn2;
        __syncthreads();

        #pragma unroll
        for (int ks = 0; ks < 8; ++ks) {
            unsigned a[4];
            const unsigned* pp = &Ps[rowA*68 + ks*8 + lc];
            a[0] = pp[0]; a[1] = pp[8*68]; a[2] = pp[4]; a[3] = pp[8*68 + 4];
            #pragma unroll
            for (int nt = 0; nt < 8; ++nt) {
                unsigned bf[2];
                bf[0] = Vs[(ks*8 + lc)*72 + nt*8 + lr];
                bf[1] = Vs[(ks*8 + lc + 4)*72 + nt*8 + lr];
                mma8(oacc[nt], a, bf);
            }
        }
    }

    // epilogue: memory branch via mma on sigma(Q) fragments
    __syncthreads();
    const float* Mg = M_in + (size_t)bh*DH*DH;
    for (int i = tid; i < DH*DH; i += 256) {
        int d = i >> 6, v = i & 63;
        Ks[v*68 + d] = f2tf(Mg[i]);       // Ms[v][d]
    }
    if (tid < DH) Zs[tid] = Z_in[bh*DH + tid];
    __syncthreads();

    float macc[8][4];
    #pragma unroll
    for (int i = 0; i < 8; i++) { macc[i][0]=0.f; macc[i][1]=0.f; macc[i][2]=0.f; macc[i][3]=0.f; }
    float den1 = 0.f, den2 = 0.f;

    #pragma unroll
    for (int ks = 0; ks < 8; ++ks) {
        unsigned a[4];
        float s0 = sigma_f(__uint_as_float(qa[ks][0]));
        float s1 = sigma_f(__uint_as_float(qa[ks][1]));
        float s2 = sigma_f(__uint_as_float(qa[ks][2]));
        float s3 = sigma_f(__uint_as_float(qa[ks][3]));
        a[0] = f2tf(s0); a[1] = f2tf(s1); a[2] = f2tf(s2); a[3] = f2tf(s3);
        den1 += s0*Zs[ks*8+lc] + s2*Zs[ks*8+lc+4];
        den2 += s1*Zs[ks*8+lc] + s3*Zs[ks*8+lc+4];
        #pragma unroll
        for (int nt = 0; nt < 8; ++nt) {
            unsigned bf[2];
            const unsigned* mp = &Ks[(nt*8 + lr)*68 + ks*8 + lc];
            bf[0] = mp[0]; bf[1] = mp[4];
            mma8(macc[nt], a, bf);
        }
    }
    den1 += __shfl_xor_sync(0xffffffffu, den1, 1);
    den1 += __shfl_xor_sync(0xffffffffu, den1, 2);
    den2 += __shfl_xor_sync(0xffffffffu, den2, 1);
    den2 += __shfl_xor_sync(0xffffffffu, den2, 2);

    float g = 1.f / (1.f + __expf(-beta_gate[h]));
    float iv1 = 1.f/l1, iv2 = 1.f/l2, id1 = 1.f/den1, id2 = 1.f/den2;

    int n1 = qb + rowA;
    float* o1 = outA + ((size_t)(b*NQ + n1))*INNER + h*DH;
    float* o2 = o1 + (size_t)8*INNER;
    #pragma unroll
    for (int nt = 0; nt < 8; ++nt) {
        int d = nt*8 + 2*lc;
        *(float2*)&o1[d] = make_float2(
            g*macc[nt][0]*id1 + (1.f-g)*oacc[nt][0]*iv1,
            g*macc[nt][1]*id1 + (1.f-g)*oacc[nt][1]*iv1);
        *(float2*)&o2[d] = make_float2(
            g*macc[nt][2]*id2 + (1.f-g)*oacc[nt][2]*iv2,
            g*macc[nt][3]*id2 + (1.f-g)*oacc[nt][3]*iv2);
    }
}

// ---------------------------------------------------------------------------
// Kernel 3: state update (fp32). One CTA per (b,h).
// ---------------------------------------------------------------------------
#define CN 32
__global__ __launch_bounds__(256)
void state_kernel(const float* __restrict__ M_in, const float* __restrict__ Z_in,
                  const float* __restrict__ beta_lin, float* __restrict__ out) {
    __shared__ float Ms[DH][DH];
    __shared__ float Zs[DH];
    __shared__ float sks[CN][DH];
    __shared__ float dvs[CN][DH];
    __shared__ float invden[CN];

    const int tid = threadIdx.x;
    const int bh = blockIdx.x;

    const float* Mg = M_in + (size_t)bh * DH * DH;
    for (int e = tid; e < DH*DH; e += 256) Ms[e >> 6][e & 63] = Mg[e];
    if (tid < DH) Zs[tid] = Z_in[bh*DH + tid];

    const float* kg = g_k + (size_t)bh*NQ*DH;
    const float* vg = g_v + (size_t)bh*NQ*DH;

    const int dgrp = tid >> 2;
    const int vb   = (tid & 3) << 4;
    float macc[16];
    #pragma unroll
    for (int i = 0; i < 16; i++) macc[i] = 0.f;
    float zacc = 0.f;

    for (int n0 = 0; n0 < NQ; n0 += CN) {
        __syncthreads();
        #pragma unroll
        for (int i = 0; i < 2; i++) {
            int fidx = tid + 256*i;
            int n = fidx >> 4, dd = (fidx & 15) << 2;
            float4 kv = *(const float4*)&kg[(size_t)(n0+n)*DH + dd];
            kv.x = sigma_f(kv.x); kv.y = sigma_f(kv.y);
            kv.z = sigma_f(kv.z); kv.w = sigma_f(kv.w);
            *(float4*)&sks[n][dd] = kv;
            *(float4*)&dvs[n][dd] = *(const float4*)&vg[(size_t)(n0+n)*DH + dd];
        }
        __syncthreads();
        if (tid < CN) {
            float acc = 0.f;
            #pragma unroll
            for (int d = 0; d < DH; d++) acc += sks[tid][d]*Zs[d];
            invden[tid] = 1.f / acc;
        }
        __syncthreads();
        #pragma unroll
        for (int e = 0; e < 8; e++) {
            int idx = tid + 256*e;
            int n = idx >> 6, v = idx & 63;
            float acc = 0.f;
            #pragma unroll
            for (int d = 0; d < DH; d++) acc += sks[n][d]*Ms[d][v];
            dvs[n][v] -= acc * invden[n];
        }
        __syncthreads();
        #pragma unroll 4
        for (int n = 0; n < CN; n++) {
            float skdn = sks[n][dgrp];
            const float* dv = &dvs[n][vb];
            #pragma unroll
            for (int vv = 0; vv < 16; vv++) macc[vv] += skdn * dv[vv];
        }
        if (tid < DH) {
            #pragma unroll
            for (int n = 0; n < CN; n++) zacc += sks[n][tid];
        }
    }
    __syncthreads();

    float beta = 1.f / (1.f + __expf(-beta_lin[0]));
    beta = fminf(fmaxf(beta, 0.9f), 0.999f);

    float* mout = out + A_ELEMS + (size_t)bh * DH * DH;
    #pragma unroll
    for (int vv = 0; vv < 16; vv++)
        mout[dgrp*DH + vb + vv] = beta*Ms[dgrp][vb+vv] + macc[vv];
    if (tid < DH)
        out[A_ELEMS + M_ELEMS + bh*DH + tid] = beta*Zs[tid] + zacc;
}

// ---------------------------------------------------------------------------
extern "C" void kernel_launch(void* const* d_in, const int* in_sizes, int n_in,
                              void* d_out, int out_size) {
    const float* x         = (const float*)d_in[0];
    const float* M         = (const float*)d_in[1];
    const float* Z         = (const float*)d_in[2];
    const float* W         = (const float*)d_in[3];
    const float* beta_lin  = (const float*)d_in[4];
    const float* beta_gate = (const float*)d_in[5];
    float* out = (float*)d_out;

    cudaFuncSetAttribute(attn_k, cudaFuncAttributeMaxDynamicSharedMemorySize, ATT_SMEM_BYTES);

    qkv_gemm<<<dim3(NCOLS/128, (BB*NQ)/128), 256>>>(x, W);
    attn_k<<<dim3(NQ/128, HEADS, BB), 256, ATT_SMEM_BYTES>>>(M, Z, beta_gate, out);
    state_kernel<<<BB*HEADS, 256>>>(M, Z, beta_lin, out);
}

// round 4
// speedup vs baseline: 3.8108x; 1.6395x over previous
#include <cuda_runtime.h>

#define BB    4
#define NQ    2048
#define DIMK  1024
#define HEADS 16
#define DH    64
#define INNER 1024
#define NCOLS 3072
#define SPLIT 4

#define A_ELEMS (BB*NQ*INNER)
#define M_ELEMS (BB*HEADS*DH*DH)

__device__ float g_q[BB*HEADS*NQ*DH];
__device__ float g_k[BB*HEADS*NQ*DH];
__device__ float g_v[BB*HEADS*NQ*DH];
__device__ float g_mpart[BB*HEADS*SPLIT*DH*DH];
__device__ float g_zpart[BB*HEADS*SPLIT*DH];

__device__ __forceinline__ unsigned f2tf(float f) {
    unsigned u; asm("cvt.rna.tf32.f32 %0, %1;" : "=r"(u) : "f"(f)); return u;
}
__device__ __forceinline__ void mma8(float* c, const unsigned* a, const unsigned* b) {
    asm volatile(
        "mma.sync.aligned.m16n8k8.row.col.f32.tf32.tf32.f32 "
        "{%0,%1,%2,%3}, {%4,%5,%6,%7}, {%8,%9}, {%0,%1,%2,%3};\n"
        : "+f"(c[0]), "+f"(c[1]), "+f"(c[2]), "+f"(c[3])
        : "r"(a[0]), "r"(a[1]), "r"(a[2]), "r"(a[3]), "r"(b[0]), "r"(b[1]));
}
__device__ __forceinline__ float sigma_f(float f) {
    return (f > 0.f) ? (f + 1.f) : __expf(f);
}

// ---------------------------------------------------------------------------
// Kernel 1: QKV GEMM (tf32, 2-stage double-buffered smem, 1 sync per k-tile)
// ---------------------------------------------------------------------------
__global__ __launch_bounds__(256, 2)
void qkv_gemm(const float* __restrict__ x, const float* __restrict__ W) {
    __shared__ __align__(16) unsigned As[2][128*20];
    __shared__ __align__(16) unsigned Bs[2][16*136];

    const int tid  = threadIdx.x;
    const int bm   = blockIdx.y * 128, bn = blockIdx.x * 128;
    const int wid  = tid >> 5, lane = tid & 31;
    const int wm   = (wid & 1) * 64, wn = (wid >> 1) * 32;
    const int lr   = lane >> 2, lc = lane & 3;

    const int ar0 = tid >> 2;
    const int ac  = (tid & 3) << 2;
    const int bk0 = tid >> 5;
    const int bc  = (tid & 31) << 2;

    const float* ap0 = x + (size_t)(bm + ar0) * DIMK + ac;
    const float* ap1 = ap0 + (size_t)64 * DIMK;
    const float* bp0 = W + (size_t)bk0 * NCOLS + bn + bc;
    const float* bp1 = bp0 + (size_t)8 * NCOLS;

    float4 ra0 = *(const float4*)ap0;
    float4 ra1 = *(const float4*)ap1;
    float4 rb0 = *(const float4*)bp0;
    float4 rb1 = *(const float4*)bp1;

    // stage 0
    {
        unsigned* ad0 = &As[0][ar0*20 + ac];
        ad0[0]=f2tf(ra0.x); ad0[1]=f2tf(ra0.y); ad0[2]=f2tf(ra0.z); ad0[3]=f2tf(ra0.w);
        unsigned* ad1 = &As[0][(ar0+64)*20 + ac];
        ad1[0]=f2tf(ra1.x); ad1[1]=f2tf(ra1.y); ad1[2]=f2tf(ra1.z); ad1[3]=f2tf(ra1.w);
        *(uint4*)&Bs[0][bk0*136 + bc]     = make_uint4(f2tf(rb0.x), f2tf(rb0.y), f2tf(rb0.z), f2tf(rb0.w));
        *(uint4*)&Bs[0][(bk0+8)*136 + bc] = make_uint4(f2tf(rb1.x), f2tf(rb1.y), f2tf(rb1.z), f2tf(rb1.w));
    }

    float cacc[4][4][4];
    #pragma unroll
    for (int i = 0; i < 4; i++)
        #pragma unroll
        for (int j = 0; j < 4; j++) { cacc[i][j][0]=0.f; cacc[i][j][1]=0.f; cacc[i][j][2]=0.f; cacc[i][j][3]=0.f; }

    int cur = 0;
    for (int kt = 0; kt < DIMK/16; ++kt) {
        __syncthreads();
        const bool has = (kt + 1 < DIMK/16);
        if (has) {
            int ko = (kt + 1) * 16;
            ra0 = *(const float4*)(ap0 + ko);
            ra1 = *(const float4*)(ap1 + ko);
            rb0 = *(const float4*)(bp0 + (size_t)ko * NCOLS);
            rb1 = *(const float4*)(bp1 + (size_t)ko * NCOLS);
        }

        #pragma unroll
        for (int ks = 0; ks < 2; ++ks) {
            unsigned af[4][4];
            #pragma unroll
            for (int mt = 0; mt < 4; ++mt) {
                int r = wm + mt*16 + lr, k = ks*8 + lc;
                af[mt][0] = As[cur][r*20 + k];
                af[mt][1] = As[cur][(r+8)*20 + k];
                af[mt][2] = As[cur][r*20 + k + 4];
                af[mt][3] = As[cur][(r+8)*20 + k + 4];
            }
            unsigned bf[4][2];
            #pragma unroll
            for (int nt = 0; nt < 4; ++nt) {
                int c = wn + nt*8 + lr, k = ks*8 + lc;
                bf[nt][0] = Bs[cur][k*136 + c];
                bf[nt][1] = Bs[cur][(k+4)*136 + c];
            }
            #pragma unroll
            for (int mt = 0; mt < 4; ++mt)
                #pragma unroll
                for (int nt = 0; nt < 4; ++nt)
                    mma8(cacc[mt][nt], af[mt], bf[nt]);
        }

        if (has) {
            int nx = cur ^ 1;
            unsigned* ad0 = &As[nx][ar0*20 + ac];
            ad0[0]=f2tf(ra0.x); ad0[1]=f2tf(ra0.y); ad0[2]=f2tf(ra0.z); ad0[3]=f2tf(ra0.w);
            unsigned* ad1 = &As[nx][(ar0+64)*20 + ac];
            ad1[0]=f2tf(ra1.x); ad1[1]=f2tf(ra1.y); ad1[2]=f2tf(ra1.z); ad1[3]=f2tf(ra1.w);
            *(uint4*)&Bs[nx][bk0*136 + bc]     = make_uint4(f2tf(rb0.x), f2tf(rb0.y), f2tf(rb0.z), f2tf(rb0.w));
            *(uint4*)&Bs[nx][(bk0+8)*136 + bc] = make_uint4(f2tf(rb1.x), f2tf(rb1.y), f2tf(rb1.z), f2tf(rb1.w));
        }
        cur ^= 1;
    }

    #pragma unroll
    for (int mt = 0; mt < 4; ++mt) {
        int r0 = bm + wm + mt*16 + lr;
        #pragma unroll
        for (int nt = 0; nt < 4; ++nt) {
            int cg = bn + wn + nt*8 + 2*lc;
            int part = cg >> 10;
            float* dst = (part == 0) ? g_q : (part == 1) ? g_k : g_v;
            int hh = (cg >> 6) & (HEADS - 1);
            int dd = cg & 63;
            int bi = r0 >> 11, nn = r0 & 2047;
            size_t off = (((size_t)(bi*HEADS + hh) * NQ + nn) * DH) + dd;
            *(float2*)&dst[off] = make_float2(cacc[mt][nt][0], cacc[mt][nt][1]);
            int r1 = r0 + 8;
            bi = r1 >> 11; nn = r1 & 2047;
            off = (((size_t)(bi*HEADS + hh) * NQ + nn) * DH) + dd;
            *(float2*)&dst[off] = make_float2(cacc[mt][nt][2], cacc[mt][nt][3]);
        }
    }
}

// ---------------------------------------------------------------------------
// Kernel 2: flash attention v3 — no P smem (shuffle frag conversion),
// double-buffered K/V, 1 sync/iter, exp2 softmax, memory branch epilogue.
// smem: Kb[2][64*68] | Vb[2][64*72] | Zs[64]
// ---------------------------------------------------------------------------
#define ATT_SMEM_WORDS (2*64*68 + 2*64*72 + 64)
#define ATT_SMEM_BYTES (ATT_SMEM_WORDS*4)
#define SCL2 0.1803368801111204f   // 0.125 * log2(e)

__global__ __launch_bounds__(256, 2)
void attn_k(const float* __restrict__ M_in, const float* __restrict__ Z_in,
            const float* __restrict__ beta_gate, float* __restrict__ outA) {
    extern __shared__ unsigned sm[];
    unsigned* Kb0 = sm;
    unsigned* Kb1 = sm + 64*68;
    unsigned* Vb0 = sm + 2*64*68;
    unsigned* Vb1 = Vb0 + 64*72;
    float*    Zs  = (float*)(sm + 2*64*68 + 2*64*72);

    const int tid = threadIdx.x, wid = tid >> 5, lane = tid & 31;
    const int lr = lane >> 2, lc = lane & 3;
    const int b = blockIdx.z, h = blockIdx.y, bh = b*HEADS + h;
    const int qb = blockIdx.x * 128;
    const int rowA = wid*16 + lr;

    const float* qg = g_q + ((size_t)bh*NQ + qb)*DH;
    const float* kg = g_k + (size_t)bh*NQ*DH;
    const float* vg = g_v + (size_t)bh*NQ*DH;

    // Q fragments direct from global (one-time)
    unsigned qa[8][4];
    {
        const float* q0 = qg + (size_t)rowA*DH;
        const float* q1 = qg + (size_t)(rowA+8)*DH;
        #pragma unroll
        for (int ks = 0; ks < 8; ++ks) {
            qa[ks][0] = f2tf(q0[ks*8 + lc]);
            qa[ks][1] = f2tf(q1[ks*8 + lc]);
            qa[ks][2] = f2tf(q0[ks*8 + lc + 4]);
            qa[ks][3] = f2tf(q1[ks*8 + lc + 4]);
        }
    }

    // stage tile 0
    #pragma unroll
    for (int t = 0; t < 4; ++t) {
        int i = tid + 256*t;
        int r = i >> 4, c4 = (i & 15) << 2;
        float4 kv = *(const float4*)(kg + (size_t)r*DH + c4);
        *(uint4*)&Kb0[r*68 + c4] = make_uint4(f2tf(kv.x), f2tf(kv.y), f2tf(kv.z), f2tf(kv.w));
        float4 vv = *(const float4*)(vg + (size_t)r*DH + c4);
        *(uint4*)&Vb0[r*72 + c4] = make_uint4(f2tf(vv.x), f2tf(vv.y), f2tf(vv.z), f2tf(vv.w));
    }
    __syncthreads();

    float oacc[8][4];
    #pragma unroll
    for (int i = 0; i < 8; i++) { oacc[i][0]=0.f; oacc[i][1]=0.f; oacc[i][2]=0.f; oacc[i][3]=0.f; }
    float m1 = -1e30f, m2 = -1e30f, l1 = 0.f, l2 = 0.f;

    const int src  = lr*4 + (lc >> 1);
    const bool hi  = lc & 1;

    int cur = 0;
    for (int jt = 0; jt < NQ; jt += 64) {
        const bool has = (jt + 64 < NQ);
        unsigned* Kc = cur ? Kb1 : Kb0;
        unsigned* Vc = cur ? Vb1 : Vb0;
        unsigned* Kn = cur ? Kb0 : Kb1;
        unsigned* Vn = cur ? Vb0 : Vb1;

        // prefetch next K
        float4 kpre[4];
        if (has) {
            #pragma unroll
            for (int t = 0; t < 4; ++t) {
                int i = tid + 256*t;
                int r = i >> 4, c4 = (i & 15) << 2;
                kpre[t] = *(const float4*)(kg + (size_t)(jt + 64 + r)*DH + c4);
            }
        }

        // S = Q K^T
        float sacc[8][4];
        #pragma unroll
        for (int i = 0; i < 8; i++) { sacc[i][0]=0.f; sacc[i][1]=0.f; sacc[i][2]=0.f; sacc[i][3]=0.f; }
        #pragma unroll
        for (int ks = 0; ks < 8; ++ks) {
            #pragma unroll
            for (int nt = 0; nt < 8; ++nt) {
                unsigned bf[2];
                const unsigned* kp = &Kc[(nt*8 + lr)*68 + ks*8 + lc];
                bf[0] = kp[0]; bf[1] = kp[4];
                mma8(sacc[nt], qa[ks], bf);
            }
        }

        if (has) {
            #pragma unroll
            for (int t = 0; t < 4; ++t) {
                int i = tid + 256*t;
                int r = i >> 4, c4 = (i & 15) << 2;
                *(uint4*)&Kn[r*68 + c4] = make_uint4(f2tf(kpre[t].x), f2tf(kpre[t].y), f2tf(kpre[t].z), f2tf(kpre[t].w));
            }
        }

        // prefetch next V
        float4 vpre[4];
        if (has) {
            #pragma unroll
            for (int t = 0; t < 4; ++t) {
                int i = tid + 256*t;
                int r = i >> 4, c4 = (i & 15) << 2;
                vpre[t] = *(const float4*)(vg + (size_t)(jt + 64 + r)*DH + c4);
            }
        }

        // online softmax (base-2 domain)
        float tmax1 = -1e30f, tmax2 = -1e30f;
        #pragma unroll
        for (int nt = 0; nt < 8; ++nt) {
            tmax1 = fmaxf(tmax1, fmaxf(sacc[nt][0], sacc[nt][1]));
            tmax2 = fmaxf(tmax2, fmaxf(sacc[nt][2], sacc[nt][3]));
        }
        tmax1 = fmaxf(tmax1, __shfl_xor_sync(0xffffffffu, tmax1, 1));
        tmax1 = fmaxf(tmax1, __shfl_xor_sync(0xffffffffu, tmax1, 2));
        tmax2 = fmaxf(tmax2, __shfl_xor_sync(0xffffffffu, tmax2, 1));
        tmax2 = fmaxf(tmax2, __shfl_xor_sync(0xffffffffu, tmax2, 2));

        float mn1 = fmaxf(m1, tmax1*SCL2), mn2 = fmaxf(m2, tmax2*SCL2);
        float corr1 = exp2f(m1 - mn1), corr2 = exp2f(m2 - mn2);
        float rs1 = 0.f, rs2 = 0.f;
        #pragma unroll
        for (int nt = 0; nt < 8; ++nt) {
            sacc[nt][0] = exp2f(sacc[nt][0]*SCL2 - mn1);
            sacc[nt][1] = exp2f(sacc[nt][1]*SCL2 - mn1);
            sacc[nt][2] = exp2f(sacc[nt][2]*SCL2 - mn2);
            sacc[nt][3] = exp2f(sacc[nt][3]*SCL2 - mn2);
            rs1 += sacc[nt][0] + sacc[nt][1];
            rs2 += sacc[nt][2] + sacc[nt][3];
        }
        rs1 += __shfl_xor_sync(0xffffffffu, rs1, 1);
        rs1 += __shfl_xor_sync(0xffffffffu, rs1, 2);
        rs2 += __shfl_xor_sync(0xffffffffu, rs2, 1);
        rs2 += __shfl_xor_sync(0xffffffffu, rs2, 2);
        l1 = l1*corr1 + rs1;
        l2 = l2*corr2 + rs2;
        #pragma unroll
        for (int nt = 0; nt < 8; ++nt) {
            oacc[nt][0] *= corr1; oacc[nt][1] *= corr1;
            oacc[nt][2] *= corr2; oacc[nt][3] *= corr2;
        }
        m1 = mn1; m2 = mn2;

        if (has) {
            #pragma unroll
            for (int t = 0; t < 4; ++t) {
                int i = tid + 256*t;
                int r = i >> 4, c4 = (i & 15) << 2;
                *(uint4*)&Vn[r*72 + c4] = make_uint4(f2tf(vpre[t].x), f2tf(vpre[t].y), f2tf(vpre[t].z), f2tf(vpre[t].w));
            }
        }

        // O += P V : build A-fragments from C-layout via shuffles
        #pragma unroll
        for (int ks = 0; ks < 8; ++ks) {
            float e0 = __shfl_sync(0xffffffffu, sacc[ks][0], src);
            float e1 = __shfl_sync(0xffffffffu, sacc[ks][1], src);
            float e2 = __shfl_sync(0xffffffffu, sacc[ks][2], src);
            float e3 = __shfl_sync(0xffffffffu, sacc[ks][3], src);
            float f0 = __shfl_sync(0xffffffffu, sacc[ks][0], src + 2);
            float f1 = __shfl_sync(0xffffffffu, sacc[ks][1], src + 2);
            float f2v = __shfl_sync(0xffffffffu, sacc[ks][2], src + 2);
            float f3 = __shfl_sync(0xffffffffu, sacc[ks][3], src + 2);
            unsigned a[4];
            a[0] = f2tf(hi ? e1 : e0);
            a[1] = f2tf(hi ? e3 : e2);
            a[2] = f2tf(hi ? f1 : f0);
            a[3] = f2tf(hi ? f3 : f2v);
            #pragma unroll
            for (int nt = 0; nt < 8; ++nt) {
                unsigned bf[2];
                bf[0] = Vc[(ks*8 + lc)*72 + nt*8 + lr];
                bf[1] = Vc[(ks*8 + lc + 4)*72 + nt*8 + lr];
                mma8(oacc[nt], a, bf);
            }
        }
        __syncthreads();
        cur ^= 1;
    }

    // epilogue: memory branch (sigma(Q) @ M) via mma; M^T staged in Kb0
    const float* Mg = M_in + (size_t)bh*DH*DH;
    for (int i = tid; i < DH*DH; i += 256) {
        int d = i >> 6, v = i & 63;
        Kb0[v*68 + d] = f2tf(Mg[i]);
    }
    if (tid < DH) Zs[tid] = Z_in[bh*DH + tid];
    __syncthreads();

    float macc[8][4];
    #pragma unroll
    for (int i = 0; i < 8; i++) { macc[i][0]=0.f; macc[i][1]=0.f; macc[i][2]=0.f; macc[i][3]=0.f; }
    float den1 = 0.f, den2 = 0.f;

    #pragma unroll
    for (int ks = 0; ks < 8; ++ks) {
        unsigned a[4];
        float s0 = sigma_f(__uint_as_float(qa[ks][0]));
        float s1 = sigma_f(__uint_as_float(qa[ks][1]));
        float s2 = sigma_f(__uint_as_float(qa[ks][2]));
        float s3 = sigma_f(__uint_as_float(qa[ks][3]));
        a[0] = f2tf(s0); a[1] = f2tf(s1); a[2] = f2tf(s2); a[3] = f2tf(s3);
        den1 += s0*Zs[ks*8+lc] + s2*Zs[ks*8+lc+4];
        den2 += s1*Zs[ks*8+lc] + s3*Zs[ks*8+lc+4];
        #pragma unroll
        for (int nt = 0; nt < 8; ++nt) {
            unsigned bf[2];
            const unsigned* mp = &Kb0[(nt*8 + lr)*68 + ks*8 + lc];
            bf[0] = mp[0]; bf[1] = mp[4];
            mma8(macc[nt], a, bf);
        }
    }
    den1 += __shfl_xor_sync(0xffffffffu, den1, 1);
    den1 += __shfl_xor_sync(0xffffffffu, den1, 2);
    den2 += __shfl_xor_sync(0xffffffffu, den2, 1);
    den2 += __shfl_xor_sync(0xffffffffu, den2, 2);

    float g = 1.f / (1.f + __expf(-beta_gate[h]));
    float iv1 = 1.f/l1, iv2 = 1.f/l2, id1 = 1.f/den1, id2 = 1.f/den2;

    int n1 = qb + rowA;
    float* o1 = outA + ((size_t)(b*NQ + n1))*INNER + h*DH;
    float* o2 = o1 + (size_t)8*INNER;
    #pragma unroll
    for (int nt = 0; nt < 8; ++nt) {
        int d = nt*8 + 2*lc;
        *(float2*)&o1[d] = make_float2(
            g*macc[nt][0]*id1 + (1.f-g)*oacc[nt][0]*iv1,
            g*macc[nt][1]*id1 + (1.f-g)*oacc[nt][1]*iv1);
        *(float2*)&o2[d] = make_float2(
            g*macc[nt][2]*id2 + (1.f-g)*oacc[nt][2]*iv2,
            g*macc[nt][3]*id2 + (1.f-g)*oacc[nt][3]*iv2);
    }
}

// ---------------------------------------------------------------------------
// Kernel 3a: state partials, split SPLIT ways over n. grid = 64*SPLIT.
// ---------------------------------------------------------------------------
#define CN 32
__global__ __launch_bounds__(256)
void state_part(const float* __restrict__ M_in, const float* __restrict__ Z_in) {
    __shared__ float Ms[DH][DH];
    __shared__ float Zs[DH];
    __shared__ float sks[CN][DH];
    __shared__ float dvs[CN][DH];
    __shared__ float invden[CN];

    const int tid = threadIdx.x;
    const int bh = blockIdx.x >> 2;
    const int chunk = blockIdx.x & 3;
    const int nrows = NQ / SPLIT;

    const float* Mg = M_in + (size_t)bh * DH * DH;
    for (int e = tid; e < DH*DH; e += 256) Ms[e >> 6][e & 63] = Mg[e];
    if (tid < DH) Zs[tid] = Z_in[bh*DH + tid];

    const float* kg = g_k + (size_t)bh*NQ*DH + (size_t)chunk*nrows*DH;
    const float* vg = g_v + (size_t)bh*NQ*DH + (size_t)chunk*nrows*DH;

    const int dgrp = tid >> 2;
    const int vb   = (tid & 3) << 4;
    float macc[16];
    #pragma unroll
    for (int i = 0; i < 16; i++) macc[i] = 0.f;
    float zacc = 0.f;

    for (int n0 = 0; n0 < nrows; n0 += CN) {
        __syncthreads();
        #pragma unroll
        for (int i = 0; i < 2; i++) {
            int fidx = tid + 256*i;
            int n = fidx >> 4, dd = (fidx & 15) << 2;
            float4 kv = *(const float4*)&kg[(size_t)(n0+n)*DH + dd];
            kv.x = sigma_f(kv.x); kv.y = sigma_f(kv.y);
            kv.z = sigma_f(kv.z); kv.w = sigma_f(kv.w);
            *(float4*)&sks[n][dd] = kv;
            *(float4*)&dvs[n][dd] = *(const float4*)&vg[(size_t)(n0+n)*DH + dd];
        }
        __syncthreads();
        if (tid < CN) {
            float acc = 0.f;
            #pragma unroll
            for (int d = 0; d < DH; d++) acc += sks[tid][d]*Zs[d];
            invden[tid] = 1.f / acc;
        }
        __syncthreads();
        #pragma unroll
        for (int e = 0; e < 8; e++) {
            int idx = tid + 256*e;
            int n = idx >> 6, v = idx & 63;
            float acc = 0.f;
            #pragma unroll
            for (int d = 0; d < DH; d++) acc += sks[n][d]*Ms[d][v];
            dvs[n][v] -= acc * invden[n];
        }
        __syncthreads();
        #pragma unroll 4
        for (int n = 0; n < CN; n++) {
            float skdn = sks[n][dgrp];
            const float* dv = &dvs[n][vb];
            #pragma unroll
            for (int vv = 0; vv < 16; vv++) macc[vv] += skdn * dv[vv];
        }
        if (tid < DH) {
            #pragma unroll
            for (int n = 0; n < CN; n++) zacc += sks[n][tid];
        }
    }

    float* mp = g_mpart + (size_t)blockIdx.x * DH*DH;
    #pragma unroll
    for (int vv = 0; vv < 16; vv++)
        mp[dgrp*DH + vb + vv] = macc[vv];
    if (tid < DH)
        g_zpart[blockIdx.x*DH + tid] = zacc;
}

// ---------------------------------------------------------------------------
// Kernel 3b: reduce partials -> out
// ---------------------------------------------------------------------------
__global__ __launch_bounds__(256)
void state_reduce(const float* __restrict__ M_in, const float* __restrict__ Z_in,
                  const float* __restrict__ beta_lin, float* __restrict__ out) {
    const int bh = blockIdx.x;
    const int tid = threadIdx.x;
    float beta = 1.f / (1.f + __expf(-beta_lin[0]));
    beta = fminf(fmaxf(beta, 0.9f), 0.999f);

    const float* p0 = g_mpart + (size_t)(bh*4 + 0)*DH*DH;
    const float* p1 = g_mpart + (size_t)(bh*4 + 1)*DH*DH;
    const float* p2 = g_mpart + (size_t)(bh*4 + 2)*DH*DH;
    const float* p3 = g_mpart + (size_t)(bh*4 + 3)*DH*DH;
    const float* Mg = M_in + (size_t)bh*DH*DH;
    float* mo = out + A_ELEMS + (size_t)bh*DH*DH;
    for (int e = tid; e < DH*DH; e += 256)
        mo[e] = beta*Mg[e] + p0[e] + p1[e] + p2[e] + p3[e];
    if (tid < DH) {
        float z = g_zpart[(bh*4+0)*DH + tid] + g_zpart[(bh*4+1)*DH + tid]
                + g_zpart[(bh*4+2)*DH + tid] + g_zpart[(bh*4+3)*DH + tid];
        out[A_ELEMS + M_ELEMS + bh*DH + tid] = beta*Z_in[bh*DH + tid] + z;
    }
}

// ---------------------------------------------------------------------------
extern "C" void kernel_launch(void* const* d_in, const int* in_sizes, int n_in,
                              void* d_out, int out_size) {
    const float* x         = (const float*)d_in[0];
    const float* M         = (const float*)d_in[1];
    const float* Z         = (const float*)d_in[2];
    const float* W         = (const float*)d_in[3];
    const float* beta_lin  = (const float*)d_in[4];
    const float* beta_gate = (const float*)d_in[5];
    float* out = (float*)d_out;

    cudaFuncSetAttribute(attn_k, cudaFuncAttributeMaxDynamicSharedMemorySize, ATT_SMEM_BYTES);

    qkv_gemm<<<dim3(NCOLS/128, (BB*NQ)/128), 256>>>(x, W);
    attn_k<<<dim3(NQ/128, HEADS, BB), 256, ATT_SMEM_BYTES>>>(M, Z, beta_gate, out);
    state_part<<<BB*HEADS*SPLIT, 256>>>(M, Z);
    state_reduce<<<BB*HEADS, 256>>>(M, Z, beta_lin, out);
}